// round 2
// baseline (speedup 1.0000x reference)
#include <cuda_runtime.h>
#include <math.h>
#include <float.h>

#define BB 4
#define NN 4096
#define LL 256
#define KSEL 20
#define EPSF 1e-6f

// ---------------- scratch (static device globals; no allocation) ----------------
__device__ float g_xnorm[(size_t)BB * NN * LL];          // 16 MB normalized history
__device__ float g_sim[(size_t)BB * NN * NN];            // 256 MB similarity matrix

// ---------------- kernel 1: per-row mean/rms normalization ----------------
// one warp per row; 4 warps per block.  mask is int32 (bool promoted by harness).
__global__ __launch_bounds__(128) void knorm(const float* __restrict__ hist,
                                             const int* __restrict__ mask) {
    int row = blockIdx.x * 4 + (threadIdx.x >> 5);
    if (row >= BB * NN) return;
    int lane = threadIdx.x & 31;
    const float* x = hist + (size_t)row * LL;

    float v[8];
#pragma unroll
    for (int i = 0; i < 2; i++) {
        float4 t = ((const float4*)x)[lane + i * 32];
        v[i * 4 + 0] = t.x; v[i * 4 + 1] = t.y; v[i * 4 + 2] = t.z; v[i * 4 + 3] = t.w;
    }
    float s = 0.f;
#pragma unroll
    for (int i = 0; i < 8; i++) s += v[i];
#pragma unroll
    for (int off = 16; off; off >>= 1) s += __shfl_xor_sync(0xffffffffu, s, off);
    float mean = s * (1.f / LL);

    float ss = 0.f;
#pragma unroll
    for (int i = 0; i < 8; i++) { float d = v[i] - mean; ss += d * d; }
#pragma unroll
    for (int off = 16; off; off >>= 1) ss += __shfl_xor_sync(0xffffffffu, ss, off);

    float denom = fmaxf(sqrtf(ss * (1.f / LL)), EPSF);
    float scale = (mask[row] != 0 ? 1.f : 0.f) / denom;

    float* o = g_xnorm + (size_t)row * LL;
#pragma unroll
    for (int i = 0; i < 2; i++) {
        float4 t;
        t.x = (v[i * 4 + 0] - mean) * scale;
        t.y = (v[i * 4 + 1] - mean) * scale;
        t.z = (v[i * 4 + 2] - mean) * scale;
        t.w = (v[i * 4 + 3] - mean) * scale;
        ((float4*)o)[lane + i * 32] = t;
    }
}

// ---------------- kernel 2: sim = relu(X X^T / L), zero diag ----------------
#define BM 128
#define BN 128
#define BKC 8
__global__ __launch_bounds__(256) void kgemm() {
    int b = blockIdx.z;
    int tileM = blockIdx.y * BM;
    int tileN = blockIdx.x * BN;
    const float* __restrict__ X = g_xnorm + (size_t)b * NN * LL;
    float* __restrict__ C = g_sim + (size_t)b * NN * NN;

    __shared__ float As[2][BKC][BM];
    __shared__ float Bs[2][BKC][BN];

    int tid = threadIdx.x;
    int tx = tid & 15;      // 0..15 -> n micro
    int ty = tid >> 4;      // 0..15 -> m micro

    int lrow = tid >> 1;        // 0..127
    int lk4  = (tid & 1) * 4;   // 0 or 4

    float acc[8][8];
#pragma unroll
    for (int i = 0; i < 8; i++)
#pragma unroll
        for (int j = 0; j < 8; j++) acc[i][j] = 0.f;

    const int nch = LL / BKC;   // 32

    // prologue load chunk 0
    {
        float4 a = *(const float4*)(X + (size_t)(tileM + lrow) * LL + lk4);
        As[0][lk4 + 0][lrow] = a.x; As[0][lk4 + 1][lrow] = a.y;
        As[0][lk4 + 2][lrow] = a.z; As[0][lk4 + 3][lrow] = a.w;
        float4 bq = *(const float4*)(X + (size_t)(tileN + lrow) * LL + lk4);
        Bs[0][lk4 + 0][lrow] = bq.x; Bs[0][lk4 + 1][lrow] = bq.y;
        Bs[0][lk4 + 2][lrow] = bq.z; Bs[0][lk4 + 3][lrow] = bq.w;
    }
    __syncthreads();

    for (int ch = 0; ch < nch; ch++) {
        int buf = ch & 1;
        if (ch + 1 < nch) {
            int k0 = (ch + 1) * BKC;
            float4 a = *(const float4*)(X + (size_t)(tileM + lrow) * LL + k0 + lk4);
            As[buf ^ 1][lk4 + 0][lrow] = a.x; As[buf ^ 1][lk4 + 1][lrow] = a.y;
            As[buf ^ 1][lk4 + 2][lrow] = a.z; As[buf ^ 1][lk4 + 3][lrow] = a.w;
            float4 bq = *(const float4*)(X + (size_t)(tileN + lrow) * LL + k0 + lk4);
            Bs[buf ^ 1][lk4 + 0][lrow] = bq.x; Bs[buf ^ 1][lk4 + 1][lrow] = bq.y;
            Bs[buf ^ 1][lk4 + 2][lrow] = bq.z; Bs[buf ^ 1][lk4 + 3][lrow] = bq.w;
        }
#pragma unroll
        for (int kk = 0; kk < BKC; kk++) {
            float af[8], bf[8];
            *(float4*)(af)     = *(const float4*)&As[buf][kk][ty * 8];
            *(float4*)(af + 4) = *(const float4*)&As[buf][kk][ty * 8 + 4];
            *(float4*)(bf)     = *(const float4*)&Bs[buf][kk][tx * 8];
            *(float4*)(bf + 4) = *(const float4*)&Bs[buf][kk][tx * 8 + 4];
#pragma unroll
            for (int i = 0; i < 8; i++)
#pragma unroll
                for (int j = 0; j < 8; j++) acc[i][j] = fmaf(af[i], bf[j], acc[i][j]);
        }
        __syncthreads();
    }

    const float inv_l = 1.f / LL;
#pragma unroll
    for (int i = 0; i < 8; i++) {
        int gm = tileM + ty * 8 + i;
        float* crow = C + (size_t)gm * NN + tileN + tx * 8;
#pragma unroll
        for (int j4 = 0; j4 < 2; j4++) {
            float4 r;
            float vv[4];
#pragma unroll
            for (int q = 0; q < 4; q++) {
                int j = j4 * 4 + q;
                int gn = tileN + tx * 8 + j;
                float v = fmaxf(acc[i][j] * inv_l, 0.f);
                if (gm == gn) v = 0.f;
                vv[q] = v;
            }
            r.x = vv[0]; r.y = vv[1]; r.z = vv[2]; r.w = vv[3];
            *(float4*)(crow + j4 * 4) = r;
        }
    }
}

// ---------------- kernel 3: per-row top-20 + double row-normalize + dense write ----
#define TPB3 128
__global__ __launch_bounds__(TPB3) void ktopk(const int* __restrict__ mask,
                                              float* __restrict__ out) {
    int b = blockIdx.y;
    int row = blockIdx.x;
    const float* simrow = g_sim + ((size_t)b * NN + row) * NN;
    float* orow = out + ((size_t)b * NN + row) * NN;
    const int* mrow = mask + (size_t)b * NN;

    __shared__ float sv[NN];
    __shared__ float rv[TPB3 / 32];
    __shared__ int   ri[TPB3 / 32];
    __shared__ float sel_v[KSEL];
    __shared__ int   sel_i[KSEL];
    __shared__ float fscale;

    int tid = threadIdx.x;

    // load row; masked columns -> -FLT_MAX (like -inf in the reference; clamped to 0 later)
    for (int i = tid; i < NN; i += TPB3) {
        float v = simrow[i];
        if (mrow[i] == 0) v = -FLT_MAX;
        sv[i] = v;
    }
    __syncthreads();

    for (int it = 0; it < KSEL; it++) {
        float bv = -INFINITY;
        int bi = 0x7fffffff;
        for (int i = tid; i < NN; i += TPB3) {
            float v = sv[i];
            if (v > bv) { bv = v; bi = i; }   // ascending scan -> lowest index per thread
        }
#pragma unroll
        for (int off = 16; off; off >>= 1) {
            float ov = __shfl_xor_sync(0xffffffffu, bv, off);
            int   oi = __shfl_xor_sync(0xffffffffu, bi, off);
            if (ov > bv || (ov == bv && oi < bi)) { bv = ov; bi = oi; }
        }
        int w = tid >> 5;
        if ((tid & 31) == 0) { rv[w] = bv; ri[w] = bi; }
        __syncthreads();
        if (tid == 0) {
#pragma unroll
            for (int w2 = 1; w2 < TPB3 / 32; w2++) {
                if (rv[w2] > bv || (rv[w2] == bv && ri[w2] < bi)) { bv = rv[w2]; bi = ri[w2]; }
            }
            sel_v[it] = bv;
            sel_i[it] = bi;
            sv[bi] = -INFINITY;   // remove; strictly below -FLT_MAX so never re-picked
        }
        __syncthreads();
    }

    if (tid == 0) {
        // vals = where(finite, vals, 0); zero diag; both row-normalizes exactly
        float S = 0.f;
#pragma unroll
        for (int t = 0; t < KSEL; t++) {
            float v = sel_v[t];
            if (v < 0.f) v = 0.f;            // covers -FLT_MAX (masked) and relu'd values
            if (sel_i[t] == row) v = 0.f;    // diagonal excluded
            sel_v[t] = v;
            S += v;
        }
        float r1 = 1.f / fmaxf(S, EPSF);
        float S1 = S * r1;                   // row sum after first normalize
        float r2 = 1.f / fmaxf(S1, EPSF);
        fscale = r1 * r2;
    }
    __syncthreads();

    // build final row in shared, then coalesced write
    for (int i = tid; i < NN; i += TPB3) sv[i] = 0.f;
    __syncthreads();
    if (tid < KSEL) sv[sel_i[tid]] = sel_v[tid] * fscale;
    __syncthreads();

    for (int i = tid * 4; i < NN; i += TPB3 * 4) {
        *(float4*)(orow + i) = *(const float4*)(sv + i);
    }
}

// ---------------- launch ----------------
extern "C" void kernel_launch(void* const* d_in, const int* in_sizes, int n_in,
                              void* d_out, int out_size) {
    const float* hist = (const float*)d_in[0];
    const int* mask = (const int*)d_in[1];
    float* out = (float*)d_out;

    knorm<<<(BB * NN) / 4, 128>>>(hist, mask);

    dim3 g2(NN / BN, NN / BM, BB);
    kgemm<<<g2, 256>>>();

    dim3 g3(NN, BB);
    ktopk<<<g3, TPB3>>>(mask, out);
}

// round 4
// speedup vs baseline: 2.0236x; 2.0236x over previous
#include <cuda_runtime.h>
#include <math.h>
#include <float.h>
#include <stdint.h>

#define BB 4
#define NN 4096
#define LL 256
#define KSEL 20
#define EPSF 1e-6f

// ---------------- scratch (static device globals; no allocation) ----------------
__device__ float g_xhi[(size_t)BB * NN * LL];            // tf32-rounded normalized history
__device__ float g_xlo[(size_t)BB * NN * LL];            // tf32 residual
__device__ float g_sim[(size_t)BB * NN * NN];            // 256 MB similarity matrix
__device__ uint32_t g_maskbits[BB * (NN / 32)];          // column mask as bits

// ---------------- kernel 0: mask -> bitmask ----------------
__global__ void kmask(const int* __restrict__ mask) {
    int b = blockIdx.x;
    int t = threadIdx.x;            // 0..127
    uint32_t w = 0;
#pragma unroll
    for (int q = 0; q < 32; q++)
        w |= (mask[b * NN + t * 32 + q] != 0 ? 1u : 0u) << q;
    g_maskbits[b * (NN / 32) + t] = w;
}

// ---------------- kernel 1: per-row normalization + tf32 hi/lo split ----------------
__global__ __launch_bounds__(128) void knorm(const float* __restrict__ hist,
                                             const int* __restrict__ mask) {
    int row = blockIdx.x * 4 + (threadIdx.x >> 5);
    if (row >= BB * NN) return;
    int lane = threadIdx.x & 31;
    const float* x = hist + (size_t)row * LL;

    float v[8];
#pragma unroll
    for (int i = 0; i < 2; i++) {
        float4 t = ((const float4*)x)[lane + i * 32];
        v[i * 4 + 0] = t.x; v[i * 4 + 1] = t.y; v[i * 4 + 2] = t.z; v[i * 4 + 3] = t.w;
    }
    float s = 0.f;
#pragma unroll
    for (int i = 0; i < 8; i++) s += v[i];
#pragma unroll
    for (int off = 16; off; off >>= 1) s += __shfl_xor_sync(0xffffffffu, s, off);
    float mean = s * (1.f / LL);

    float ss = 0.f;
#pragma unroll
    for (int i = 0; i < 8; i++) { float d = v[i] - mean; ss += d * d; }
#pragma unroll
    for (int off = 16; off; off >>= 1) ss += __shfl_xor_sync(0xffffffffu, ss, off);

    float denom = fmaxf(sqrtf(ss * (1.f / LL)), EPSF);
    float scale = (mask[row] != 0 ? 1.f : 0.f) / denom;

    float* ohi = g_xhi + (size_t)row * LL;
    float* olo = g_xlo + (size_t)row * LL;
#pragma unroll
    for (int i = 0; i < 2; i++) {
        float4 thi, tlo;
#pragma unroll
        for (int q = 0; q < 4; q++) {
            float y = (v[i * 4 + q] - mean) * scale;
            unsigned uhi;
            asm("cvt.rna.tf32.f32 %0, %1;" : "=r"(uhi) : "f"(y));
            float hi = __uint_as_float(uhi);
            float r = y - hi;                   // exact
            unsigned ulo;
            asm("cvt.rna.tf32.f32 %0, %1;" : "=r"(ulo) : "f"(r));
            ((float*)&thi)[q] = hi;
            ((float*)&tlo)[q] = __uint_as_float(ulo);
        }
        ((float4*)ohi)[lane + i * 32] = thi;
        ((float4*)olo)[lane + i * 32] = tlo;
    }
}

// ---------------- kernel 2: 3xTF32 tensor-core GEMM, upper tiles + transpose ----
#define BM 128
#define BN 128
#define BK 32
#define NTILE (NN / BM)                  // 32
#define NUPPER (NTILE * (NTILE + 1) / 2) // 528
#define TSTRIDE 132                      // transpose staging row stride (floats)

__device__ __forceinline__ void mma_tf32(float* d, const float* a, const float* b) {
    asm volatile(
        "mma.sync.aligned.m16n8k8.row.col.f32.tf32.tf32.f32 "
        "{%0,%1,%2,%3}, {%4,%5,%6,%7}, {%8,%9}, {%0,%1,%2,%3};"
        : "+f"(d[0]), "+f"(d[1]), "+f"(d[2]), "+f"(d[3])
        : "r"(__float_as_uint(a[0])), "r"(__float_as_uint(a[1])),
          "r"(__float_as_uint(a[2])), "r"(__float_as_uint(a[3])),
          "r"(__float_as_uint(b[0])), "r"(__float_as_uint(b[1])));
}

#define CPA16(dst32, src) \
    asm volatile("cp.async.cg.shared.global [%0], [%1], 16;\n" :: "r"(dst32), "l"(src))

__global__ __launch_bounds__(256, 1) void kgemm() {
    extern __shared__ float smem[];
    float* As_hi = smem;                  // [2][128][32]
    float* As_lo = smem + 8192;
    float* Bs_hi = smem + 16384;
    float* Bs_lo = smem + 24576;
    float* smem_t = smem;                 // reused after mainloop (128*132 floats)

    // map linear tile id -> (ti, tj) upper triangular (tj >= ti)
    int t = blockIdx.x;
    int ti = 0;
    while (t >= NTILE - ti) { t -= NTILE - ti; ti++; }
    int tj = ti + t;

    int b = blockIdx.z;
    int tileM = ti * BM;
    int tileN = tj * BN;
    const float* __restrict__ Xh = g_xhi + (size_t)b * NN * LL;
    const float* __restrict__ Xl = g_xlo + (size_t)b * NN * LL;
    float* __restrict__ C = g_sim + (size_t)b * NN * NN;

    int tid = threadIdx.x;
    int wid = tid >> 5;
    int lane = tid & 31;
    int g = lane >> 2;        // 0..7
    int tg = lane & 3;        // 0..3
    int m0w = (wid & 1) * 64;
    int n0w = (wid >> 1) * 32;

    // loader mapping: 256 threads -> 128 rows x 2 f4-halves
    int lm  = tid >> 1;
    int lf4 = (tid & 1) * 4;
    const float* gAh = Xh + (size_t)(tileM + lm) * LL;
    const float* gAl = Xl + (size_t)(tileM + lm) * LL;
    const float* gBh = Xh + (size_t)(tileN + lm) * LL;
    const float* gBl = Xl + (size_t)(tileN + lm) * LL;
    uint32_t base = (uint32_t)__cvta_generic_to_shared(smem);
    uint32_t sAh = base + (0 * 8192 + lm * BK) * 4;
    uint32_t sAl = base + (1 * 8192 + lm * BK) * 4;
    uint32_t sBh = base + (2 * 8192 + lm * BK) * 4;
    uint32_t sBl = base + (3 * 8192 + lm * BK) * 4;
    int msw = lm & 7;

    float acc[4][4][4];
#pragma unroll
    for (int i = 0; i < 4; i++)
#pragma unroll
        for (int j = 0; j < 4; j++)
#pragma unroll
            for (int q = 0; q < 4; q++) acc[i][j][q] = 0.f;

    const int NKB = LL / BK;   // 8

#pragma unroll
    for (int q = 0; q < 4; q++) {
        int f4 = lf4 + q;
        int f4s = (f4 ^ msw) * 16;
        CPA16(sAh + f4s, gAh + f4 * 4);
        CPA16(sAl + f4s, gAl + f4 * 4);
        CPA16(sBh + f4s, gBh + f4 * 4);
        CPA16(sBl + f4s, gBl + f4 * 4);
    }
    asm volatile("cp.async.commit_group;");
    asm volatile("cp.async.wait_group 0;");
    __syncthreads();

    for (int kb = 0; kb < NKB; kb++) {
        int buf = kb & 1;
        if (kb + 1 < NKB) {
            uint32_t off = (buf ^ 1) * BM * BK * 4;
            int k0 = (kb + 1) * BK;
#pragma unroll
            for (int q = 0; q < 4; q++) {
                int f4 = lf4 + q;
                int f4s = (f4 ^ msw) * 16;
                CPA16(sAh + off + f4s, gAh + k0 + f4 * 4);
                CPA16(sAl + off + f4s, gAl + k0 + f4 * 4);
                CPA16(sBh + off + f4s, gBh + k0 + f4 * 4);
                CPA16(sBl + off + f4s, gBl + k0 + f4 * 4);
            }
            asm volatile("cp.async.commit_group;");
        }

        const float* Abh = As_hi + buf * BM * BK;
        const float* Abl = As_lo + buf * BM * BK;
        const float* Bbh = Bs_hi + buf * BM * BK;
        const float* Bbl = Bs_lo + buf * BM * BK;
#pragma unroll
        for (int ks = 0; ks < 4; ks++) {
            float ah[4][4], al[4][4];
#pragma unroll
            for (int i = 0; i < 4; i++) {
                int r0 = m0w + i * 16 + g;
                int r1 = r0 + 8;
                int o00 = r0 * BK + ((2 * ks)     ^ (r0 & 7)) * 4 + tg;
                int o01 = r1 * BK + ((2 * ks)     ^ (r1 & 7)) * 4 + tg;
                int o10 = r0 * BK + ((2 * ks + 1) ^ (r0 & 7)) * 4 + tg;
                int o11 = r1 * BK + ((2 * ks + 1) ^ (r1 & 7)) * 4 + tg;
                ah[i][0] = Abh[o00]; ah[i][1] = Abh[o01];
                ah[i][2] = Abh[o10]; ah[i][3] = Abh[o11];
                al[i][0] = Abl[o00]; al[i][1] = Abl[o01];
                al[i][2] = Abl[o10]; al[i][3] = Abl[o11];
            }
            float bh[4][2], bl[4][2];
#pragma unroll
            for (int j = 0; j < 4; j++) {
                int nb = n0w + j * 8 + g;
                int o0 = nb * BK + ((2 * ks)     ^ (nb & 7)) * 4 + tg;
                int o1 = nb * BK + ((2 * ks + 1) ^ (nb & 7)) * 4 + tg;
                bh[j][0] = Bbh[o0]; bh[j][1] = Bbh[o1];
                bl[j][0] = Bbl[o0]; bl[j][1] = Bbl[o1];
            }
#pragma unroll
            for (int i = 0; i < 4; i++)
#pragma unroll
                for (int j = 0; j < 4; j++) {
                    mma_tf32(acc[i][j], ah[i], bh[j]);   // hi*hi
                    mma_tf32(acc[i][j], ah[i], bl[j]);   // hi*lo
                    mma_tf32(acc[i][j], al[i], bh[j]);   // lo*hi
                }
        }

        if (kb + 1 < NKB) asm volatile("cp.async.wait_group 0;");
        __syncthreads();
    }

    // epilogue: scale, relu, zero-diag
    const float inv_l = 1.f / LL;
#pragma unroll
    for (int i = 0; i < 4; i++) {
        int gm0 = tileM + m0w + i * 16 + g;
        int gm1 = gm0 + 8;
#pragma unroll
        for (int j = 0; j < 4; j++) {
            int gn = tileN + n0w + j * 8 + 2 * tg;
            float v0 = fmaxf(acc[i][j][0] * inv_l, 0.f);
            float v1 = fmaxf(acc[i][j][1] * inv_l, 0.f);
            float v2 = fmaxf(acc[i][j][2] * inv_l, 0.f);
            float v3 = fmaxf(acc[i][j][3] * inv_l, 0.f);
            if (gm0 == gn)     v0 = 0.f;
            if (gm0 == gn + 1) v1 = 0.f;
            if (gm1 == gn)     v2 = 0.f;
            if (gm1 == gn + 1) v3 = 0.f;
            acc[i][j][0] = v0; acc[i][j][1] = v1;
            acc[i][j][2] = v2; acc[i][j][3] = v3;
            float2 r0 = {v0, v1}, r1 = {v2, v3};
            *(float2*)(C + (size_t)gm0 * NN + gn) = r0;
            *(float2*)(C + (size_t)gm1 * NN + gn) = r1;
        }
    }

    // mirror tile via smem transpose (off-diagonal only)
    if (ti != tj) {
        // mainloop ended with __syncthreads; As/Bs free to reuse
#pragma unroll
        for (int i = 0; i < 4; i++) {
            int ml0 = m0w + i * 16 + g;
            int ml1 = ml0 + 8;
#pragma unroll
            for (int j = 0; j < 4; j++) {
                int nl = n0w + j * 8 + 2 * tg;
                smem_t[(nl)     * TSTRIDE + ml0] = acc[i][j][0];
                smem_t[(nl + 1) * TSTRIDE + ml0] = acc[i][j][1];
                smem_t[(nl)     * TSTRIDE + ml1] = acc[i][j][2];
                smem_t[(nl + 1) * TSTRIDE + ml1] = acc[i][j][3];
            }
        }
        __syncthreads();
#pragma unroll
        for (int it = 0; it < 16; it++) {
            int idx = it * 256 + tid;          // 0..4095
            int r = idx >> 5;                  // 0..127 (n_local)
            int c4 = idx & 31;                 // float4 column
            float4 v = *(const float4*)&smem_t[r * TSTRIDE + c4 * 4];
            *(float4*)(C + (size_t)(tileN + r) * NN + tileM + c4 * 4) = v;
        }
    }
}

// ---------------- kernel 3: tournament top-20 + double row-normalize ------------
#define TPB3 128
__global__ __launch_bounds__(TPB3) void ktopk(float* __restrict__ out) {
    int b = blockIdx.y;
    int row = blockIdx.x;
    const float* simrow = g_sim + ((size_t)b * NN + row) * NN;
    float* orow = out + ((size_t)b * NN + row) * NN;
    const uint32_t* mbits = g_maskbits + b * (NN / 32);

    __shared__ float sv[NN];
    __shared__ float cv[TPB3];
    __shared__ int   ci[TPB3];
    __shared__ float sel_v[KSEL];
    __shared__ int   sel_i[KSEL];
    __shared__ float fscale;

    int tid = threadIdx.x;
    int lane = tid & 31;

    // load row with column mask (bitmask in L2/L1)
    for (int i = tid * 4; i < NN; i += TPB3 * 4) {
        float4 v = *(const float4*)(simrow + i);
        uint32_t mb = (mbits[i >> 5] >> (i & 31)) & 0xFu;
        if (!(mb & 1u)) v.x = -FLT_MAX;
        if (!(mb & 2u)) v.y = -FLT_MAX;
        if (!(mb & 4u)) v.z = -FLT_MAX;
        if (!(mb & 8u)) v.w = -FLT_MAX;
        *(float4*)(sv + i) = v;
    }
    __syncthreads();

    // chunk maxima: chunk t = indices { t + 128*j }
    {
        float bv = -INFINITY; int bi = 0x7fffffff;
#pragma unroll 8
        for (int j = 0; j < NN / TPB3; j++) {
            int idx = tid + TPB3 * j;
            float v = sv[idx];
            if (v > bv) { bv = v; bi = idx; }
        }
        cv[tid] = bv; ci[tid] = bi;
    }
    __syncthreads();

    if (tid < 32) {
        for (int it = 0; it < KSEL; it++) {
            float bv = cv[lane]; int bi = ci[lane];
#pragma unroll
            for (int t2 = 1; t2 < 4; t2++) {
                float v = cv[lane + 32 * t2]; int i2 = ci[lane + 32 * t2];
                if (v > bv || (v == bv && i2 < bi)) { bv = v; bi = i2; }
            }
#pragma unroll
            for (int off = 16; off; off >>= 1) {
                float ov = __shfl_xor_sync(0xffffffffu, bv, off);
                int   oi = __shfl_xor_sync(0xffffffffu, bi, off);
                if (ov > bv || (ov == bv && oi < bi)) { bv = ov; bi = oi; }
            }
            if (lane == 0) {
                sel_v[it] = bv;
                sel_i[it] = bi;
                sv[bi] = -INFINITY;
            }
            __syncwarp();
            int c = bi & (TPB3 - 1);
            int idx = c + TPB3 * lane;
            float nv = sv[idx]; int ni = idx;
#pragma unroll
            for (int off = 16; off; off >>= 1) {
                float ov = __shfl_xor_sync(0xffffffffu, nv, off);
                int   oi = __shfl_xor_sync(0xffffffffu, ni, off);
                if (ov > nv || (ov == nv && oi < ni)) { nv = ov; ni = oi; }
            }
            if (lane == 0) { cv[c] = nv; ci[c] = ni; }
            __syncwarp();
        }
    }
    __syncthreads();

    if (tid == 0) {
        float S = 0.f;
#pragma unroll
        for (int t2 = 0; t2 < KSEL; t2++) {
            float v = sel_v[t2];
            if (v < 0.f) v = 0.f;
            if (sel_i[t2] == row) v = 0.f;
            sel_v[t2] = v;
            S += v;
        }
        float r1 = 1.f / fmaxf(S, EPSF);
        float S1 = S * r1;
        float r2 = 1.f / fmaxf(S1, EPSF);
        fscale = r1 * r2;
    }
    __syncthreads();

    for (int i = tid; i < NN; i += TPB3) sv[i] = 0.f;
    __syncthreads();
    if (tid < KSEL) sv[sel_i[tid]] = sel_v[tid] * fscale;
    __syncthreads();

    for (int i = tid * 4; i < NN; i += TPB3 * 4) {
        *(float4*)(orow + i) = *(const float4*)(sv + i);
    }
}

// ---------------- launch ----------------
extern "C" void kernel_launch(void* const* d_in, const int* in_sizes, int n_in,
                              void* d_out, int out_size) {
    const float* hist = (const float*)d_in[0];
    const int* mask = (const int*)d_in[1];
    float* out = (float*)d_out;

    static int smem_set = 0;
    if (!smem_set) {
        cudaFuncSetAttribute(kgemm, cudaFuncAttributeMaxDynamicSharedMemorySize,
                             131072);
        smem_set = 1;
    }

    kmask<<<BB, NN / 32>>>(mask);
    knorm<<<(BB * NN) / 4, 128>>>(hist, mask);

    dim3 g2(NUPPER, 1, BB);
    kgemm<<<g2, 256, 131072>>>();

    dim3 g3(NN, BB);
    ktopk<<<g3, TPB3>>>(out);
}